// round 2
// baseline (speedup 1.0000x reference)
#include <cuda_runtime.h>

#define Bn   16
#define Tn   32
#define INn  112
#define Hn   512
#define NGn  7
#define On   8
#define En   409      // int(0.8*512)
#define EXn  410      // H - round(0.2*512)
#define AWc   0.02f
#define OMAWc 0.98f
#define AXc   0.2f
#define OMAXc 0.8f
#define DTc   0.02f
#define WBc   10.0f

struct __align__(16) SM {
    float awbh[64 * Hn];    // alpha_w * relu(w_h2h) rows of this CTA
    float awbx[64 * INn];   // alpha_w * relu(w_x2h)
    float xs[Tn * INn];     // x[t, b, :] preloaded
    float wa[NGn * Hn];     // plastic attn weights (CTA rank 0 only)
    float awba[NGn * Hn];
    float effo[On * Hn];    // relu(w_h2o) * exist
    float effv[Hn];         // relu(w_h2v) * exist
    float out[Hn];          // out(t-1) raw
    float os[Hn];           // sign-masked out(t-1)
    float xg[INn];
    float attn[8];
    float logits[8];
    float battn[8];
    float kap[24];
    float Rs[Tn];
};

__device__ float g_outv[Bn * Hn];
__device__ float g_attnv[Bn * 8];

__device__ __forceinline__ float warp_sum(float v) {
    v += __shfl_xor_sync(0xffffffffu, v, 16);
    v += __shfl_xor_sync(0xffffffffu, v, 8);
    v += __shfl_xor_sync(0xffffffffu, v, 4);
    v += __shfl_xor_sync(0xffffffffu, v, 2);
    v += __shfl_xor_sync(0xffffffffu, v, 1);
    return v;
}
__device__ __forceinline__ float warp_max(float v) {
    v = fmaxf(v, __shfl_xor_sync(0xffffffffu, v, 16));
    v = fmaxf(v, __shfl_xor_sync(0xffffffffu, v, 8));
    v = fmaxf(v, __shfl_xor_sync(0xffffffffu, v, 4));
    v = fmaxf(v, __shfl_xor_sync(0xffffffffu, v, 2));
    v = fmaxf(v, __shfl_xor_sync(0xffffffffu, v, 1));
    return v;
}

__global__ void __launch_bounds__(512, 1) __cluster_dims__(8, 1, 1)
rnn_kernel(const float* __restrict__ x, const float* __restrict__ R,
           const float* __restrict__ w_x2h, const float* __restrict__ w_h2h,
           const float* __restrict__ b_h2h, const float* __restrict__ w_attn,
           const float* __restrict__ b_attn, const float* __restrict__ w_h2o,
           const float* __restrict__ w_h2v, const float* __restrict__ kappa,
           float* __restrict__ yout)
{
    extern __shared__ __align__(16) char smraw[];
    SM& s = *reinterpret_cast<SM*>(smraw);

    const int tid  = threadIdx.x;
    const int w    = tid >> 5;
    const int l    = tid & 31;
    const int rank = blockIdx.x & 7;
    const int b    = blockIdx.x >> 3;
    const int rl0  = w * 4;            // local row base in CTA (0..60)
    const int row0 = rank * 64 + rl0;  // global row base

    // ---------------- init ----------------
    if (tid < 24) s.kap[tid]   = (tid < 21)  ? kappa[tid]  : 0.f;
    if (tid < 8)  s.battn[tid] = (tid < NGn) ? b_attn[tid] : 0.f;
    if (tid < Tn) s.Rs[tid]    = R[tid * Bn + b];
    for (int i = tid; i < Tn * INn; i += 512)
        s.xs[i] = x[((i / INn) * Bn + b) * INn + (i % INn)];
    s.out[tid] = 0.f;
    s.os[tid]  = 0.f;

    float wh[4][16];
    float wxr[4][4] = {{0,0,0,0},{0,0,0,0},{0,0,0,0},{0,0,0,0}};
    float bh[4], wd[4], awbd[4];
    bool  rhb[4];

    #pragma unroll
    for (int r = 0; r < 4; r++) {
        const int row = row0 + r;
        bh[r]  = b_h2h[row];
        rhb[r] = (row >= En);
        float dv = fmaxf(w_h2h[row * Hn + row], 0.f);
        wd[r] = dv; awbd[r] = AWc * dv;
        #pragma unroll
        for (int c4 = 0; c4 < 4; c4++) {
            const int j0 = c4 * 128 + l * 4;
            float4 v = *reinterpret_cast<const float4*>(&w_h2h[row * Hn + j0]);
            v.x = fmaxf(v.x, 0.f); v.y = fmaxf(v.y, 0.f);
            v.z = fmaxf(v.z, 0.f); v.w = fmaxf(v.w, 0.f);
            wh[r][c4*4+0] = v.x; wh[r][c4*4+1] = v.y;
            wh[r][c4*4+2] = v.z; wh[r][c4*4+3] = v.w;
            *reinterpret_cast<float4*>(&s.awbh[(rl0 + r) * Hn + j0]) =
                make_float4(AWc*v.x, AWc*v.y, AWc*v.z, AWc*v.w);
        }
        if (l < 28) {
            const int i0 = l * 4;
            float4 v = *reinterpret_cast<const float4*>(&w_x2h[row * INn + i0]);
            v.x = fmaxf(v.x, 0.f); v.y = fmaxf(v.y, 0.f);
            v.z = fmaxf(v.z, 0.f); v.w = fmaxf(v.w, 0.f);
            wxr[r][0] = v.x; wxr[r][1] = v.y; wxr[r][2] = v.z; wxr[r][3] = v.w;
            *reinterpret_cast<float4*>(&s.awbx[(rl0 + r) * INn + i0]) =
                make_float4(AWc*v.x, AWc*v.y, AWc*v.z, AWc*v.w);
        }
    }
    if (rank == 0) {
        for (int i = tid; i < NGn * Hn; i += 512) {
            float v = fmaxf(w_attn[i], 0.f);
            s.wa[i] = v; s.awba[i] = AWc * v;
        }
        for (int i = tid; i < On * Hn; i += 512) {
            int h = i & 511;
            s.effo[i] = (h < EXn) ? fmaxf(w_h2o[i], 0.f) : 0.f;
        }
        s.effv[tid] = (tid < EXn) ? fmaxf(w_h2v[tid], 0.f) : 0.f;
    }

    float state[4] = {0.f, 0.f, 0.f, 0.f};
    const int lk = l * 4;  // base column offset within 128-block

    __syncthreads();
    const float kinA = s.kap[4 + 2 * (l >> 2)];
    const float kinB = s.kap[5 + 2 * (l >> 2)];
    const float k00 = s.kap[0], k01 = s.kap[1], k10 = s.kap[2], k11 = s.kap[3];

    // ---------------- time loop ----------------
    for (int t = 0; t < Tn; t++) {
        const float dtR = DTc * s.Rs[t];

        // --- CTA rank 0: attention from out(t-1) ---
        if (rank == 0) {
            if (w < NGn) {
                float p = 0.f;
                #pragma unroll 4
                for (int it = 0; it < 16; it++) {
                    int h = it * 32 + l;
                    float o = s.os[h];
                    if (h >= EXn) o = 0.f;
                    p = fmaf(s.wa[w * Hn + h], o, p);
                }
                p = warp_sum(p);
                if (l == 0) s.logits[w] = p;
            }
            __syncthreads();
            if (w == 0) {
                float L = (l < NGn) ? s.logits[l] + s.battn[l] : -3.4e38f;
                float mx = warp_max(L);
                float e = (l < NGn) ? expf(L - mx) : 0.f;
                float ssum = warp_sum(e);
                float a = e / ssum;
                if (l < NGn) { s.attn[l] = a; __stcg(&g_attnv[b * 8 + l], a); }
            }
            __syncthreads();
        }

        asm volatile("barrier.cluster.arrive.aligned;" ::: "memory");   // A arrive

        // --- recurrent matvec on out(t-1), overlaps barrier A ---
        float part[4] = {0.f, 0.f, 0.f, 0.f};
        #pragma unroll
        for (int c4 = 0; c4 < 4; c4++) {
            float4 ov = *reinterpret_cast<const float4*>(&s.os[c4 * 128 + lk]);
            #pragma unroll
            for (int r = 0; r < 4; r++) {
                part[r] = fmaf(wh[r][c4*4+0], ov.x, part[r]);
                part[r] = fmaf(wh[r][c4*4+1], ov.y, part[r]);
                part[r] = fmaf(wh[r][c4*4+2], ov.z, part[r]);
                part[r] = fmaf(wh[r][c4*4+3], ov.w, part[r]);
            }
        }
        float osrow[4], orow[4];
        #pragma unroll
        for (int r = 0; r < 4; r++) { osrow[r] = s.os[row0 + r]; orow[r] = s.out[row0 + r]; }

        asm volatile("barrier.cluster.wait.aligned;" ::: "memory");     // A wait

        // --- attn -> gated input ---
        if (tid < NGn) s.attn[tid] = __ldcg(&g_attnv[b * 8 + tid]);
        __syncthreads();
        if (tid < INn) s.xg[tid] = s.xs[t * INn + tid] * s.attn[tid >> 4];
        __syncthreads();

        float4 xv = make_float4(0.f, 0.f, 0.f, 0.f);
        if (l < 28) xv = *reinterpret_cast<const float4*>(&s.xg[lk]);
        #pragma unroll
        for (int r = 0; r < 4; r++) {
            part[r] = fmaf(wxr[r][0], xv.x, part[r]);
            part[r] = fmaf(wxr[r][1], xv.y, part[r]);
            part[r] = fmaf(wxr[r][2], xv.z, part[r]);
            part[r] = fmaf(wxr[r][3], xv.w, part[r]);
        }

        // --- reduce, state update, out_n ---
        float outn[4];
        #pragma unroll
        for (int r = 0; r < 4; r++) {
            float tot = warp_sum(part[r]);
            tot = tot - wd[r] * osrow[r] + bh[r];   // remove diagonal, add bias
            state[r] = fmaf(AXc, tot, OMAXc * state[r]);
        }
        {
            float st = (l == 0) ? state[0] : (l == 1) ? state[1] : (l == 2) ? state[2] : state[3];
            float tv = tanhf(fmaxf(st, 0.f));
            outn[0] = __shfl_sync(0xffffffffu, tv, 0);
            outn[1] = __shfl_sync(0xffffffffu, tv, 1);
            outn[2] = __shfl_sync(0xffffffffu, tv, 2);
            outn[3] = __shfl_sync(0xffffffffu, tv, 3);
        }
        if (l < 4) {
            float ov = (l == 0) ? outn[0] : (l == 1) ? outn[1] : (l == 2) ? outn[2] : outn[3];
            __stcg(&g_outv[b * Hn + row0 + l], ov);
        }

        asm volatile("barrier.cluster.arrive.aligned;" ::: "memory");   // B arrive

        // --- plastic weight updates (hidden behind barrier B) ---
        float cA[4], dC[4], cX[4];
        #pragma unroll
        for (int r = 0; r < 4; r++) {
            float base = dtR * outn[r];
            cA[r] = base * (rhb[r] ? k10 : k00);
            float cBr = base * (rhb[r] ? k11 : k01);
            dC[r] = cBr - cA[r];
            cX[r] = base * (rhb[r] ? kinB : kinA);
        }
        #pragma unroll
        for (int c4 = 0; c4 < 4; c4++) {
            float4 ov = *reinterpret_cast<const float4*>(&s.out[c4 * 128 + lk]);
            float m0 = 0.f, m1 = 0.f, m2 = 0.f, m3 = 0.f;
            if (c4 == 3) {   // column-half boundary at j = 409 (j = 384 + lk + k)
                m0 = (lk + 0 >= 25) ? 1.f : 0.f;
                m1 = (lk + 1 >= 25) ? 1.f : 0.f;
                m2 = (lk + 2 >= 25) ? 1.f : 0.f;
                m3 = (lk + 3 >= 25) ? 1.f : 0.f;
            }
            #pragma unroll
            for (int r = 0; r < 4; r++) {
                float4 ab = *reinterpret_cast<const float4*>(&s.awbh[(rl0 + r) * Hn + c4 * 128 + lk]);
                float c0 = fmaf(m0, dC[r], cA[r]);
                float c1 = fmaf(m1, dC[r], cA[r]);
                float c2 = fmaf(m2, dC[r], cA[r]);
                float c3 = fmaf(m3, dC[r], cA[r]);
                float v0 = fmaf(wh[r][c4*4+0], OMAWc, ab.x); v0 = fmaf(c0, ov.x, v0);
                float v1 = fmaf(wh[r][c4*4+1], OMAWc, ab.y); v1 = fmaf(c1, ov.y, v1);
                float v2 = fmaf(wh[r][c4*4+2], OMAWc, ab.z); v2 = fmaf(c2, ov.z, v2);
                float v3 = fmaf(wh[r][c4*4+3], OMAWc, ab.w); v3 = fmaf(c3, ov.w, v3);
                wh[r][c4*4+0] = fminf(fmaxf(v0, 0.f), WBc);
                wh[r][c4*4+1] = fminf(fmaxf(v1, 0.f), WBc);
                wh[r][c4*4+2] = fminf(fmaxf(v2, 0.f), WBc);
                wh[r][c4*4+3] = fminf(fmaxf(v3, 0.f), WBc);
            }
        }
        // diagonal shadow: identical recurrence to its (masked-out) array slot
        #pragma unroll
        for (int r = 0; r < 4; r++) {
            float cd = rhb[r] ? fmaf(1.f, dC[r], cA[r]) : cA[r];
            float v  = fmaf(wd[r], OMAWc, awbd[r]);
            v = fmaf(cd, orow[r], v);
            wd[r] = fminf(fmaxf(v, 0.f), WBc);
        }
        if (l < 28) {
            #pragma unroll
            for (int r = 0; r < 4; r++) {
                float4 ab = *reinterpret_cast<const float4*>(&s.awbx[(rl0 + r) * INn + lk]);
                float v0 = fmaf(wxr[r][0], OMAWc, ab.x); v0 = fmaf(cX[r], xv.x, v0);
                float v1 = fmaf(wxr[r][1], OMAWc, ab.y); v1 = fmaf(cX[r], xv.y, v1);
                float v2 = fmaf(wxr[r][2], OMAWc, ab.z); v2 = fmaf(cX[r], xv.z, v2);
                float v3 = fmaf(wxr[r][3], OMAWc, ab.w); v3 = fmaf(cX[r], xv.w, v3);
                wxr[r][0] = fminf(fmaxf(v0, 0.f), WBc);
                wxr[r][1] = fminf(fmaxf(v1, 0.f), WBc);
                wxr[r][2] = fminf(fmaxf(v2, 0.f), WBc);
                wxr[r][3] = fminf(fmaxf(v3, 0.f), WBc);
            }
        }

        asm volatile("barrier.cluster.wait.aligned;" ::: "memory");     // B wait
        __syncthreads();   // all CTA threads done reading s.out before refill

        // --- refill out(t) from global ---
        {
            float o = __ldcg(&g_outv[b * Hn + tid]);
            s.out[tid] = o;
            s.os[tid]  = (tid < En) ? o : -o;
        }
        __syncthreads();

        // --- CTA rank 0: readout + attn-weight update ---
        if (rank == 0) {
            if (w < 9) {
                const float* ew = (w < 8) ? &s.effo[w * Hn] : s.effv;
                float p = 0.f;
                #pragma unroll 4
                for (int it = 0; it < 16; it++) {
                    int h = it * 32 + l;
                    p = fmaf(ew[h], s.out[h], p);
                }
                p = warp_sum(p);
                if (l == 0) yout[(t * Bn + b) * 9 + w] = p;
            }
            float hedge = (tid < En) ? s.out[tid] : 0.f;
            #pragma unroll
            for (int kk = 0; kk < NGn; kk++) {
                int idx = kk * Hn + tid;
                float hb = dtR * s.kap[18 + kk / 3] * s.attn[kk];
                float v = fmaf(s.wa[idx], OMAWc, s.awba[idx]);
                v = fmaf(hb, hedge, v);
                s.wa[idx] = fminf(fmaxf(v, 0.f), WBc);
            }
            __syncthreads();   // wa/out ready for next step's attention
        }
    }
}

extern "C" void kernel_launch(void* const* d_in, const int* in_sizes, int n_in,
                              void* d_out, int out_size) {
    (void)in_sizes; (void)n_in; (void)out_size;
    const size_t smem = sizeof(SM);
    cudaFuncSetAttribute(rnn_kernel, cudaFuncAttributeMaxDynamicSharedMemorySize, (int)smem);
    rnn_kernel<<<Bn * 8, 512, smem>>>(
        (const float*)d_in[0], (const float*)d_in[1], (const float*)d_in[2],
        (const float*)d_in[3], (const float*)d_in[4], (const float*)d_in[5],
        (const float*)d_in[6], (const float*)d_in[7], (const float*)d_in[8],
        (const float*)d_in[9], (float*)d_out);
}

// round 4
// speedup vs baseline: 1.2058x; 1.2058x over previous
#include <cuda_runtime.h>
#include <cstdint>

#define Bn   16
#define Tn   32
#define INn  112
#define Hn   512
#define NGn  7
#define En   409      // int(0.8*512)
#define EXn  410      // H - round(0.2*512)
#define AWc   0.02f
#define OMAWc 0.98f
#define AXc   0.2f
#define OMAXc 0.8f
#define DTc   0.02f
#define WBc   10.0f

struct __align__(16) SM {
    float awbh[64 * Hn];    // alpha_w * relu(w_h2h) rows of this CTA
    float awbx[64 * INn];   // alpha_w * relu(w_x2h)
    float xs[Tn * INn];     // x[t, b, :] preloaded
    float wa[NGn * Hn];     // plastic attn weights (replicated per CTA)
    float awba[NGn * Hn];
    float effc[Hn];         // relu(w_h2o[rank]) * exist  (this rank's channel)
    float effv[Hn];         // relu(w_h2v) * exist
    float o[2][Hn];         // ping-pong raw out
    float os[2][Hn];        // ping-pong sign-masked out
    float xg[128];
    float attn[8];
    float logits[8];
    float battn[8];
    float kap[24];
    float Rs[Tn];
};

__device__ __forceinline__ float warp_sum(float v) {
    v += __shfl_xor_sync(0xffffffffu, v, 16);
    v += __shfl_xor_sync(0xffffffffu, v, 8);
    v += __shfl_xor_sync(0xffffffffu, v, 4);
    v += __shfl_xor_sync(0xffffffffu, v, 2);
    v += __shfl_xor_sync(0xffffffffu, v, 1);
    return v;
}
__device__ __forceinline__ float warp_max(float v) {
    v = fmaxf(v, __shfl_xor_sync(0xffffffffu, v, 16));
    v = fmaxf(v, __shfl_xor_sync(0xffffffffu, v, 8));
    v = fmaxf(v, __shfl_xor_sync(0xffffffffu, v, 4));
    v = fmaxf(v, __shfl_xor_sync(0xffffffffu, v, 2));
    v = fmaxf(v, __shfl_xor_sync(0xffffffffu, v, 1));
    return v;
}
__device__ __forceinline__ unsigned int smem_u32(const void* p) {
    unsigned int a;
    asm("{ .reg .u64 t; cvta.to.shared.u64 t, %1; cvt.u32.u64 %0, t; }" : "=r"(a) : "l"(p));
    return a;
}
__device__ __forceinline__ void st_clu(unsigned int laddr, int rank, float v) {
    unsigned int ra;
    asm volatile("mapa.shared::cluster.u32 %0, %1, %2;" : "=r"(ra) : "r"(laddr), "r"(rank));
    asm volatile("st.shared::cluster.f32 [%0], %1;" :: "r"(ra), "f"(v) : "memory");
}

__global__ void __launch_bounds__(512, 1) __cluster_dims__(8, 1, 1)
rnn_kernel(const float* __restrict__ x, const float* __restrict__ R,
           const float* __restrict__ w_x2h, const float* __restrict__ w_h2h,
           const float* __restrict__ b_h2h, const float* __restrict__ w_attn,
           const float* __restrict__ b_attn, const float* __restrict__ w_h2o,
           const float* __restrict__ w_h2v, const float* __restrict__ kappa,
           float* __restrict__ yout)
{
    extern __shared__ __align__(16) char smraw[];
    SM& s = *reinterpret_cast<SM*>(smraw);

    const int tid  = threadIdx.x;
    const int w    = tid >> 5;
    const int l    = tid & 31;
    const int rank = blockIdx.x & 7;
    const int b    = blockIdx.x >> 3;
    const int rl0  = w * 4;            // local row base in CTA (0..60)
    const int row0 = rank * 64 + rl0;  // global row base
    const int lk   = l * 4;            // column base within a 128-block

    // ---------------- init ----------------
    if (tid < 24) s.kap[tid]   = (tid < 21)  ? kappa[tid]  : 0.f;
    if (tid < 8)  s.battn[tid] = (tid < NGn) ? b_attn[tid] : 0.f;
    if (tid < Tn) s.Rs[tid]    = R[tid * Bn + b];
    for (int i = tid; i < Tn * INn; i += 512)
        s.xs[i] = x[((i / INn) * Bn + b) * INn + (i % INn)];
    s.o[0][tid]  = 0.f;
    s.os[0][tid] = 0.f;
    if (tid < 128) s.xg[tid] = 0.f;
    for (int i = tid; i < NGn * Hn; i += 512) {
        float v = fmaxf(w_attn[i], 0.f);
        s.wa[i] = v; s.awba[i] = AWc * v;
    }
    s.effc[tid] = (tid < EXn) ? fmaxf(w_h2o[rank * Hn + tid], 0.f) : 0.f;
    s.effv[tid] = (tid < EXn) ? fmaxf(w_h2v[tid], 0.f) : 0.f;

    float wh[4][16];
    float wxr[4][4] = {{0,0,0,0},{0,0,0,0},{0,0,0,0},{0,0,0,0}};
    float bh[4], wd[4], awbd[4];
    bool  rhb[4];

    #pragma unroll
    for (int r = 0; r < 4; r++) {
        const int row = row0 + r;
        bh[r]  = b_h2h[row];
        rhb[r] = (row >= En);
        float dv = fmaxf(w_h2h[row * Hn + row], 0.f);
        wd[r] = dv; awbd[r] = AWc * dv;
        #pragma unroll
        for (int c4 = 0; c4 < 4; c4++) {
            const int j0 = c4 * 128 + lk;
            float4 v = *reinterpret_cast<const float4*>(&w_h2h[row * Hn + j0]);
            v.x = fmaxf(v.x, 0.f); v.y = fmaxf(v.y, 0.f);
            v.z = fmaxf(v.z, 0.f); v.w = fmaxf(v.w, 0.f);
            wh[r][c4*4+0] = v.x; wh[r][c4*4+1] = v.y;
            wh[r][c4*4+2] = v.z; wh[r][c4*4+3] = v.w;
            *reinterpret_cast<float4*>(&s.awbh[(rl0 + r) * Hn + j0]) =
                make_float4(AWc*v.x, AWc*v.y, AWc*v.z, AWc*v.w);
        }
        if (l < 28) {
            const int i0 = lk;
            float4 v = *reinterpret_cast<const float4*>(&w_x2h[row * INn + i0]);
            v.x = fmaxf(v.x, 0.f); v.y = fmaxf(v.y, 0.f);
            v.z = fmaxf(v.z, 0.f); v.w = fmaxf(v.w, 0.f);
            wxr[r][0] = v.x; wxr[r][1] = v.y; wxr[r][2] = v.z; wxr[r][3] = v.w;
            *reinterpret_cast<float4*>(&s.awbx[(rl0 + r) * INn + i0]) =
                make_float4(AWc*v.x, AWc*v.y, AWc*v.z, AWc*v.w);
        }
    }

    float state[4] = {0.f, 0.f, 0.f, 0.f};

    __syncthreads();
    const float kinA = s.kap[4 + 2 * (l >> 2)];
    const float kinB = s.kap[5 + 2 * (l >> 2)];
    const float k00 = s.kap[0], k01 = s.kap[1], k10 = s.kap[2], k11 = s.kap[3];

    // all cluster CTAs done with smem init before any cross-CTA pushes
    asm volatile("barrier.cluster.arrive.aligned;" ::: "memory");
    asm volatile("barrier.cluster.wait.aligned;"   ::: "memory");

    // ---------------- time loop ----------------
    for (int t = 0; t < Tn; t++) {
        const int ib = t & 1;          // buffer holding out(t-1)
        const int ob = ib ^ 1;         // buffer receiving out(t)
        const float dtR = DTc * s.Rs[t];

        // --- wa plastic update, deferred from step t-1 (needs out(t-1)) ---
        if (t > 0) {
            const float pdtR = DTc * s.Rs[t - 1];
            const float hedge = (tid < En) ? s.o[ib][tid] : 0.f;
            #pragma unroll
            for (int kk = 0; kk < NGn; kk++) {
                const int idx = kk * Hn + tid;
                const float hb = pdtR * s.kap[18 + kk / 3] * s.attn[kk];
                float v = fmaf(s.wa[idx], OMAWc, s.awba[idx]);
                v = fmaf(hb, hedge, v);
                s.wa[idx] = fminf(fmaxf(v, 0.f), WBc);
            }
        }
        __syncthreads();

        // --- logits (warps 0-6) || readout of step t-1 (warps 14,15) ---
        if (w < NGn) {
            const float* war = &s.wa[w * Hn];
            float p = 0.f;
            #pragma unroll 4
            for (int it = 0; it < 16; it++) {
                const int h = it * 32 + l;
                float o = s.os[ib][h];
                if (h >= EXn) o = 0.f;
                p = fmaf(war[h], o, p);
            }
            p = warp_sum(p);
            if (l == 0) s.logits[w] = p;
        } else if (t > 0 && (w == 15 || (w == 14 && rank == 0))) {
            const float* ew = (w == 15) ? s.effc : s.effv;
            const int ch = (w == 15) ? rank : 8;
            float p = 0.f;
            #pragma unroll 4
            for (int it = 0; it < 16; it++) {
                const int h = it * 32 + l;
                p = fmaf(ew[h], s.o[ib][h], p);
            }
            p = warp_sum(p);
            if (l == 0) yout[((t - 1) * Bn + b) * 9 + ch] = p;
        }
        __syncthreads();

        // --- softmax (warp 0) ---
        if (w == 0) {
            float L = (l < NGn) ? s.logits[l] + s.battn[l] : -3.4e38f;
            float mx = warp_max(L);
            float e = (l < NGn) ? expf(L - mx) : 0.f;
            float ssum = warp_sum(e);
            if (l < NGn) s.attn[l] = e / ssum;
        }
        __syncthreads();

        // --- gated input ---
        if (tid < INn) s.xg[tid] = s.xs[t * INn + tid] * s.attn[tid >> 4];
        __syncthreads();

        // --- recurrent + input matvec ---
        float part[4] = {0.f, 0.f, 0.f, 0.f};
        #pragma unroll
        for (int c4 = 0; c4 < 4; c4++) {
            float4 ov = *reinterpret_cast<const float4*>(&s.os[ib][c4 * 128 + lk]);
            #pragma unroll
            for (int r = 0; r < 4; r++) {
                part[r] = fmaf(wh[r][c4*4+0], ov.x, part[r]);
                part[r] = fmaf(wh[r][c4*4+1], ov.y, part[r]);
                part[r] = fmaf(wh[r][c4*4+2], ov.z, part[r]);
                part[r] = fmaf(wh[r][c4*4+3], ov.w, part[r]);
            }
        }
        float4 xv = make_float4(0.f, 0.f, 0.f, 0.f);
        if (l < 28) xv = *reinterpret_cast<const float4*>(&s.xg[lk]);
        #pragma unroll
        for (int r = 0; r < 4; r++) {
            part[r] = fmaf(wxr[r][0], xv.x, part[r]);
            part[r] = fmaf(wxr[r][1], xv.y, part[r]);
            part[r] = fmaf(wxr[r][2], xv.z, part[r]);
            part[r] = fmaf(wxr[r][3], xv.w, part[r]);
        }

        float osrow[4], orow[4];
        #pragma unroll
        for (int r = 0; r < 4; r++) {
            osrow[r] = s.os[ib][row0 + r];
            orow[r]  = s.o[ib][row0 + r];
        }

        // --- reduce, state update, out(t) ---
        float outn[4];
        #pragma unroll
        for (int r = 0; r < 4; r++) {
            float tot = warp_sum(part[r]);
            tot = tot - wd[r] * osrow[r] + bh[r];   // remove diagonal, add bias
            state[r] = fmaf(AXc, tot, OMAXc * state[r]);
        }
        float tv;
        {
            float st = (l == 0) ? state[0] : (l == 1) ? state[1] : (l == 2) ? state[2] : state[3];
            tv = tanhf(fmaxf(st, 0.f));
            outn[0] = __shfl_sync(0xffffffffu, tv, 0);
            outn[1] = __shfl_sync(0xffffffffu, tv, 1);
            outn[2] = __shfl_sync(0xffffffffu, tv, 2);
            outn[3] = __shfl_sync(0xffffffffu, tv, 3);
        }

        // --- push out(t) / os(t) to all 8 cluster CTAs (lane l -> row l&3, rank l>>2) ---
        {
            const int rr   = l & 3;
            const int trk  = l >> 2;
            const int row  = row0 + rr;
            const float val  = __shfl_sync(0xffffffffu, tv, rr);
            const float sval = (row < En) ? val : -val;
            st_clu(smem_u32(&s.o[ob][row]),  trk, val);
            st_clu(smem_u32(&s.os[ob][row]), trk, sval);
        }

        // --- pre-load hebb operands from o[ib] BEFORE arrive (peers push o[ob] only) ---
        float4 hov[4];
        #pragma unroll
        for (int c4 = 0; c4 < 4; c4++)
            hov[c4] = *reinterpret_cast<const float4*>(&s.o[ib][c4 * 128 + lk]);

        asm volatile("barrier.cluster.arrive.aligned;" ::: "memory");

        // --- plastic wh/wx updates (hidden behind the cluster barrier) ---
        float cA[4], dC[4], cX[4];
        #pragma unroll
        for (int r = 0; r < 4; r++) {
            const float base = dtR * outn[r];
            cA[r] = base * (rhb[r] ? k10 : k00);
            const float cBr = base * (rhb[r] ? k11 : k01);
            dC[r] = cBr - cA[r];
            cX[r] = base * (rhb[r] ? kinB : kinA);
        }
        #pragma unroll
        for (int c4 = 0; c4 < 4; c4++) {
            const float4 ov = hov[c4];
            float m0 = 0.f, m1 = 0.f, m2 = 0.f, m3 = 0.f;
            if (c4 == 3) {   // column-half boundary at j = 409 (j = 384 + lk + k)
                m0 = (lk + 0 >= 25) ? 1.f : 0.f;
                m1 = (lk + 1 >= 25) ? 1.f : 0.f;
                m2 = (lk + 2 >= 25) ? 1.f : 0.f;
                m3 = (lk + 3 >= 25) ? 1.f : 0.f;
            }
            #pragma unroll
            for (int r = 0; r < 4; r++) {
                const float4 ab = *reinterpret_cast<const float4*>(
                    &s.awbh[(rl0 + r) * Hn + c4 * 128 + lk]);
                const float c0 = fmaf(m0, dC[r], cA[r]);
                const float c1 = fmaf(m1, dC[r], cA[r]);
                const float c2 = fmaf(m2, dC[r], cA[r]);
                const float c3 = fmaf(m3, dC[r], cA[r]);
                float v0 = fmaf(wh[r][c4*4+0], OMAWc, ab.x); v0 = fmaf(c0, ov.x, v0);
                float v1 = fmaf(wh[r][c4*4+1], OMAWc, ab.y); v1 = fmaf(c1, ov.y, v1);
                float v2 = fmaf(wh[r][c4*4+2], OMAWc, ab.z); v2 = fmaf(c2, ov.z, v2);
                float v3 = fmaf(wh[r][c4*4+3], OMAWc, ab.w); v3 = fmaf(c3, ov.w, v3);
                wh[r][c4*4+0] = fminf(fmaxf(v0, 0.f), WBc);
                wh[r][c4*4+1] = fminf(fmaxf(v1, 0.f), WBc);
                wh[r][c4*4+2] = fminf(fmaxf(v2, 0.f), WBc);
                wh[r][c4*4+3] = fminf(fmaxf(v3, 0.f), WBc);
            }
        }
        // diagonal shadow: identical recurrence to its (masked-out) array slot
        #pragma unroll
        for (int r = 0; r < 4; r++) {
            const float cd = rhb[r] ? (cA[r] + dC[r]) : cA[r];
            float v = fmaf(wd[r], OMAWc, awbd[r]);
            v = fmaf(cd, orow[r], v);
            wd[r] = fminf(fmaxf(v, 0.f), WBc);
        }
        if (l < 28) {
            #pragma unroll
            for (int r = 0; r < 4; r++) {
                const float4 ab = *reinterpret_cast<const float4*>(
                    &s.awbx[(rl0 + r) * INn + lk]);
                float v0 = fmaf(wxr[r][0], OMAWc, ab.x); v0 = fmaf(cX[r], xv.x, v0);
                float v1 = fmaf(wxr[r][1], OMAWc, ab.y); v1 = fmaf(cX[r], xv.y, v1);
                float v2 = fmaf(wxr[r][2], OMAWc, ab.z); v2 = fmaf(cX[r], xv.z, v2);
                float v3 = fmaf(wxr[r][3], OMAWc, ab.w); v3 = fmaf(cX[r], xv.w, v3);
                wxr[r][0] = fminf(fmaxf(v0, 0.f), WBc);
                wxr[r][1] = fminf(fmaxf(v1, 0.f), WBc);
                wxr[r][2] = fminf(fmaxf(v2, 0.f), WBc);
                wxr[r][3] = fminf(fmaxf(v3, 0.f), WBc);
            }
        }

        asm volatile("barrier.cluster.wait.aligned;" ::: "memory");
    }

    // --- final readout for t = Tn-1 (out(31) sits in buffer 0) ---
    if (w == 15 || (w == 14 && rank == 0)) {
        const float* ew = (w == 15) ? s.effc : s.effv;
        const int ch = (w == 15) ? rank : 8;
        float p = 0.f;
        #pragma unroll 4
        for (int it = 0; it < 16; it++) {
            const int h = it * 32 + l;
            p = fmaf(ew[h], s.o[0][h], p);
        }
        p = warp_sum(p);
        if (l == 0) yout[((Tn - 1) * Bn + b) * 9 + ch] = p;
    }
}

extern "C" void kernel_launch(void* const* d_in, const int* in_sizes, int n_in,
                              void* d_out, int out_size) {
    (void)in_sizes; (void)n_in; (void)out_size;
    const size_t smem = sizeof(SM);
    cudaFuncSetAttribute(rnn_kernel, cudaFuncAttributeMaxDynamicSharedMemorySize, (int)smem);
    rnn_kernel<<<Bn * 8, 512, smem>>>(
        (const float*)d_in[0], (const float*)d_in[1], (const float*)d_in[2],
        (const float*)d_in[3], (const float*)d_in[4], (const float*)d_in[5],
        (const float*)d_in[6], (const float*)d_in[7], (const float*)d_in[8],
        (const float*)d_in[9], (float*)d_out);
}

// round 5
// speedup vs baseline: 1.2842x; 1.0650x over previous
#include <cuda_runtime.h>
#include <cstdint>

#define Bn   16
#define Tn   32
#define INn  112
#define Hn   512
#define NGn  7
#define En   409      // int(0.8*512)
#define EXn  410      // H - round(0.2*512)
#define AWc   0.02f
#define OMAWc 0.98f
#define AXc   0.2f
#define OMAXc 0.8f
#define DTc   0.02f
#define WBc   10.0f

struct __align__(16) SM {
    float awbh[64 * Hn];    // alpha_w * relu(w_h2h) rows of this CTA
    float awbx[64 * INn];   // alpha_w * relu(w_x2h)
    float xs[Tn * INn];     // x[t, b, :] preloaded
    float wa[NGn * Hn];     // plastic attn weights (replicated per CTA)
    float awba[NGn * Hn];
    float effc[Hn];         // relu(w_h2o[rank]) * exist  (this rank's channel)
    float effv[Hn];         // relu(w_h2v) * exist
    float o[4][Hn];         // out(tau) lives in o[tau & 3]
    float attn[8];
    float logits2[2][8];
    float battn[8];
    float kap[24];
    float Rs[Tn];
};

__device__ __forceinline__ float warp_sum(float v) {
    v += __shfl_xor_sync(0xffffffffu, v, 16);
    v += __shfl_xor_sync(0xffffffffu, v, 8);
    v += __shfl_xor_sync(0xffffffffu, v, 4);
    v += __shfl_xor_sync(0xffffffffu, v, 2);
    v += __shfl_xor_sync(0xffffffffu, v, 1);
    return v;
}
__device__ __forceinline__ float warp_max(float v) {
    v = fmaxf(v, __shfl_xor_sync(0xffffffffu, v, 16));
    v = fmaxf(v, __shfl_xor_sync(0xffffffffu, v, 8));
    v = fmaxf(v, __shfl_xor_sync(0xffffffffu, v, 4));
    v = fmaxf(v, __shfl_xor_sync(0xffffffffu, v, 2));
    v = fmaxf(v, __shfl_xor_sync(0xffffffffu, v, 1));
    return v;
}
__device__ __forceinline__ unsigned int smem_u32(const void* p) {
    unsigned int a;
    asm("{ .reg .u64 t; cvta.to.shared.u64 t, %1; cvt.u32.u64 %0, t; }" : "=r"(a) : "l"(p));
    return a;
}
__device__ __forceinline__ void st_clu(unsigned int laddr, int rank, float v) {
    unsigned int ra;
    asm volatile("mapa.shared::cluster.u32 %0, %1, %2;" : "=r"(ra) : "r"(laddr), "r"(rank));
    asm volatile("st.shared::cluster.f32 [%0], %1;" :: "r"(ra), "f"(v) : "memory");
}

__global__ void __launch_bounds__(512, 1) __cluster_dims__(8, 1, 1)
rnn_kernel(const float* __restrict__ x, const float* __restrict__ R,
           const float* __restrict__ w_x2h, const float* __restrict__ w_h2h,
           const float* __restrict__ b_h2h, const float* __restrict__ w_attn,
           const float* __restrict__ b_attn, const float* __restrict__ w_h2o,
           const float* __restrict__ w_h2v, const float* __restrict__ kappa,
           float* __restrict__ yout)
{
    extern __shared__ __align__(16) char smraw[];
    SM& s = *reinterpret_cast<SM*>(smraw);

    const int tid  = threadIdx.x;
    const int w    = tid >> 5;
    const int l    = tid & 31;
    const int rank = blockIdx.x & 7;
    const int b    = blockIdx.x >> 3;
    const int rl0  = w * 4;            // local row base in CTA (0..60)
    const int row0 = rank * 64 + rl0;  // global row base
    const int lk   = l * 4;            // column base within a 128-block

    // ---------------- init ----------------
    if (tid < 24) s.kap[tid]   = (tid < 21)  ? kappa[tid]  : 0.f;
    if (tid < 8)  s.battn[tid] = (tid < NGn) ? b_attn[tid] : 0.f;
    if (tid < 8)  s.attn[tid]  = 0.f;
    if (tid < Tn) s.Rs[tid]    = R[tid * Bn + b];
    for (int i = tid; i < Tn * INn; i += 512)
        s.xs[i] = x[((i / INn) * Bn + b) * INn + (i % INn)];
    s.o[3][tid] = 0.f;                 // out(-1) = 0
    for (int i = tid; i < NGn * Hn; i += 512) {
        float v = fmaxf(w_attn[i], 0.f);
        s.wa[i] = v; s.awba[i] = AWc * v;
    }
    s.effc[tid] = (tid < EXn) ? fmaxf(w_h2o[rank * Hn + tid], 0.f) : 0.f;
    s.effv[tid] = (tid < EXn) ? fmaxf(w_h2v[tid], 0.f) : 0.f;

    float wh[4][16];
    float wxr[4][4] = {{0,0,0,0},{0,0,0,0},{0,0,0,0},{0,0,0,0}};
    float bh[4], wd[4], awbd[4];
    float kA[4], kD[4], kX[4];
    bool  rhb[4];

    {
        const float kinA = kappa[4 + 2 * (l >> 2)];
        const float kinB = kappa[5 + 2 * (l >> 2)];
        const float k00 = kappa[0], k01 = kappa[1], k10 = kappa[2], k11 = kappa[3];
        #pragma unroll
        for (int r = 0; r < 4; r++) {
            const int row = row0 + r;
            bh[r]  = b_h2h[row];
            rhb[r] = (row >= En);
            kA[r] = rhb[r] ? k10 : k00;
            kD[r] = (rhb[r] ? k11 : k01) - kA[r];
            kX[r] = rhb[r] ? kinB : kinA;
            float dv = fmaxf(w_h2h[row * Hn + row], 0.f);
            wd[r] = dv; awbd[r] = AWc * dv;
            #pragma unroll
            for (int c4 = 0; c4 < 4; c4++) {
                const int j0 = c4 * 128 + lk;
                float4 v = *reinterpret_cast<const float4*>(&w_h2h[row * Hn + j0]);
                v.x = fmaxf(v.x, 0.f); v.y = fmaxf(v.y, 0.f);
                v.z = fmaxf(v.z, 0.f); v.w = fmaxf(v.w, 0.f);
                wh[r][c4*4+0] = v.x; wh[r][c4*4+1] = v.y;
                wh[r][c4*4+2] = v.z; wh[r][c4*4+3] = v.w;
                *reinterpret_cast<float4*>(&s.awbh[(rl0 + r) * Hn + j0]) =
                    make_float4(AWc*v.x, AWc*v.y, AWc*v.z, AWc*v.w);
            }
            if (l < 28) {
                float4 v = *reinterpret_cast<const float4*>(&w_x2h[row * INn + lk]);
                v.x = fmaxf(v.x, 0.f); v.y = fmaxf(v.y, 0.f);
                v.z = fmaxf(v.z, 0.f); v.w = fmaxf(v.w, 0.f);
                wxr[r][0] = v.x; wxr[r][1] = v.y; wxr[r][2] = v.z; wxr[r][3] = v.w;
                *reinterpret_cast<float4*>(&s.awbx[(rl0 + r) * INn + lk]) =
                    make_float4(AWc*v.x, AWc*v.y, AWc*v.z, AWc*v.w);
            }
        }
    }

    float state[4] = {0.f, 0.f, 0.f, 0.f};

    __syncthreads();
    // all cluster CTAs done with smem init before any cross-CTA pushes
    asm volatile("barrier.cluster.arrive.aligned;" ::: "memory");
    asm volatile("barrier.cluster.wait.aligned;"   ::: "memory");

    // ---------------- time loop ----------------
    for (int t = 0; t < Tn; t++) {
        const int pb = (t + 3) & 3;    // buffer holding out(t-1)
        const int cb = t & 3;          // buffer receiving out(t)
        const float dtR = DTc * s.Rs[t];
        const float* __restrict__ op = s.o[pb];

        // --- fused: wa plastic update (deferred from t-1) + logits; readout t-1 ---
        if (w < 14) {
            const int g  = (w < 7) ? w : w - 7;
            const int h0 = (w < 7) ? 0 : 256;
            const float pdtR = (t > 0) ? DTc * s.Rs[t - 1] : 0.f;
            const float hbg  = pdtR * s.kap[18 + g / 3] * s.attn[g];
            float* __restrict__ war  = &s.wa[g * Hn];
            const float* __restrict__ abr = &s.awba[g * Hn];
            float p = 0.f;
            #pragma unroll
            for (int it = 0; it < 8; it++) {
                const int h = h0 + it * 32 + l;
                const float ov = op[h];
                const float hedge = (h < En) ? ov : 0.f;
                float v = fmaf(war[h], OMAWc, abr[h]);
                v = fmaf(hbg, hedge, v);
                v = fminf(fmaxf(v, 0.f), WBc);
                war[h] = v;
                const float osm = (h < EXn) ? ((h < En) ? ov : -ov) : 0.f;
                p = fmaf(v, osm, p);
            }
            p = warp_sum(p);
            if (l == 0) s.logits2[w >= 7][g] = p;
        } else if (t > 0 && (w == 15 || (w == 14 && rank == 0))) {
            const float* __restrict__ ew = (w == 15) ? s.effc : s.effv;
            const int ch = (w == 15) ? rank : 8;
            float p = 0.f;
            #pragma unroll 4
            for (int it = 0; it < 16; it++) {
                const int h = it * 32 + l;
                p = fmaf(ew[h], op[h], p);
            }
            p = warp_sum(p);
            if (l == 0) yout[((t - 1) * Bn + b) * 9 + ch] = p;
        }
        __syncthreads();

        // --- softmax (warp 0) ---
        if (w == 0) {
            float L = (l < NGn) ? s.logits2[0][l] + s.logits2[1][l] + s.battn[l] : -3.4e38f;
            float mx = warp_max(L);
            float e = (l < NGn) ? expf(L - mx) : 0.f;
            float ssum = warp_sum(e);
            if (l < NGn) s.attn[l] = e / ssum;
        }
        __syncthreads();

        // --- gated input (no smem pass: group l>>2 is uniform over the float4) ---
        float4 xv = make_float4(0.f, 0.f, 0.f, 0.f);
        if (l < 28) {
            xv = *reinterpret_cast<const float4*>(&s.xs[t * INn + lk]);
            const float ag = s.attn[l >> 2];
            xv.x *= ag; xv.y *= ag; xv.z *= ag; xv.w *= ag;
        }

        // --- recurrent + input matvec (sign applied analytically on c4==3) ---
        float part[4] = {0.f, 0.f, 0.f, 0.f};
        #pragma unroll
        for (int c4 = 0; c4 < 4; c4++) {
            float4 ov = *reinterpret_cast<const float4*>(&op[c4 * 128 + lk]);
            if (c4 == 3) {   // sign boundary at j = 409 (j = 384 + lk + i)
                if (lk + 0 >= 25) ov.x = -ov.x;
                if (lk + 1 >= 25) ov.y = -ov.y;
                if (lk + 2 >= 25) ov.z = -ov.z;
                if (lk + 3 >= 25) ov.w = -ov.w;
            }
            #pragma unroll
            for (int r = 0; r < 4; r++) {
                part[r] = fmaf(wh[r][c4*4+0], ov.x, part[r]);
                part[r] = fmaf(wh[r][c4*4+1], ov.y, part[r]);
                part[r] = fmaf(wh[r][c4*4+2], ov.z, part[r]);
                part[r] = fmaf(wh[r][c4*4+3], ov.w, part[r]);
            }
        }
        #pragma unroll
        for (int r = 0; r < 4; r++) {
            part[r] = fmaf(wxr[r][0], xv.x, part[r]);
            part[r] = fmaf(wxr[r][1], xv.y, part[r]);
            part[r] = fmaf(wxr[r][2], xv.z, part[r]);
            part[r] = fmaf(wxr[r][3], xv.w, part[r]);
        }

        // --- reduce, state update, out(t) ---
        float base[4];
        #pragma unroll
        for (int r = 0; r < 4; r++) {
            float tot = warp_sum(part[r]);
            const float orow = op[row0 + r];
            const float osrow = rhb[r] ? -orow : orow;
            tot = tot - wd[r] * osrow + bh[r];      // remove diagonal, add bias
            state[r] = fmaf(AXc, tot, OMAXc * state[r]);
        }
        float tv;
        {
            float st = (l == 0) ? state[0] : (l == 1) ? state[1] : (l == 2) ? state[2] : state[3];
            tv = tanhf(fmaxf(st, 0.f));
            #pragma unroll
            for (int r = 0; r < 4; r++)
                base[r] = dtR * __shfl_sync(0xffffffffu, tv, r);
        }

        // --- push out(t) to all 8 cluster CTAs (lane l -> row l&3, rank l>>2) ---
        {
            const int rr  = l & 3;
            const int trk = l >> 2;
            const float val = __shfl_sync(0xffffffffu, tv, rr);
            st_clu(smem_u32(&s.o[cb][row0 + rr]), trk, val);
        }

        asm volatile("barrier.cluster.arrive.aligned;" ::: "memory");

        // --- plastic wh/wx updates (hidden behind the cluster barrier) ---
        // safe to reload op after arrive: peers can only overwrite buffer pb
        // at their step t+3 push, which requires our arrive(t+2).
        #pragma unroll
        for (int c4 = 0; c4 < 4; c4++) {
            const float4 ov = *reinterpret_cast<const float4*>(&op[c4 * 128 + lk]);
            float m0 = 0.f, m1 = 0.f, m2 = 0.f, m3 = 0.f;
            if (c4 == 3) {   // column-half boundary at j = 409
                m0 = (lk + 0 >= 25) ? 1.f : 0.f;
                m1 = (lk + 1 >= 25) ? 1.f : 0.f;
                m2 = (lk + 2 >= 25) ? 1.f : 0.f;
                m3 = (lk + 3 >= 25) ? 1.f : 0.f;
            }
            #pragma unroll
            for (int r = 0; r < 4; r++) {
                const float4 ab = *reinterpret_cast<const float4*>(
                    &s.awbh[(rl0 + r) * Hn + c4 * 128 + lk]);
                const float cAr = base[r] * kA[r];
                const float dCr = base[r] * kD[r];
                const float c0 = fmaf(m0, dCr, cAr);
                const float c1 = fmaf(m1, dCr, cAr);
                const float c2 = fmaf(m2, dCr, cAr);
                const float c3 = fmaf(m3, dCr, cAr);
                float v0 = fmaf(wh[r][c4*4+0], OMAWc, ab.x); v0 = fmaf(c0, ov.x, v0);
                float v1 = fmaf(wh[r][c4*4+1], OMAWc, ab.y); v1 = fmaf(c1, ov.y, v1);
                float v2 = fmaf(wh[r][c4*4+2], OMAWc, ab.z); v2 = fmaf(c2, ov.z, v2);
                float v3 = fmaf(wh[r][c4*4+3], OMAWc, ab.w); v3 = fmaf(c3, ov.w, v3);
                wh[r][c4*4+0] = fminf(fmaxf(v0, 0.f), WBc);
                wh[r][c4*4+1] = fminf(fmaxf(v1, 0.f), WBc);
                wh[r][c4*4+2] = fminf(fmaxf(v2, 0.f), WBc);
                wh[r][c4*4+3] = fminf(fmaxf(v3, 0.f), WBc);
            }
        }
        // diagonal shadow: identical recurrence to its (masked-out) array slot
        #pragma unroll
        for (int r = 0; r < 4; r++) {
            const float cd = base[r] * (rhb[r] ? (kA[r] + kD[r]) : kA[r]);
            float v = fmaf(wd[r], OMAWc, awbd[r]);
            v = fmaf(cd, op[row0 + r], v);
            wd[r] = fminf(fmaxf(v, 0.f), WBc);
        }
        if (l < 28) {
            #pragma unroll
            for (int r = 0; r < 4; r++) {
                const float4 ab = *reinterpret_cast<const float4*>(
                    &s.awbx[(rl0 + r) * INn + lk]);
                const float cXr = base[r] * kX[r];
                float v0 = fmaf(wxr[r][0], OMAWc, ab.x); v0 = fmaf(cXr, xv.x, v0);
                float v1 = fmaf(wxr[r][1], OMAWc, ab.y); v1 = fmaf(cXr, xv.y, v1);
                float v2 = fmaf(wxr[r][2], OMAWc, ab.z); v2 = fmaf(cXr, xv.z, v2);
                float v3 = fmaf(wxr[r][3], OMAWc, ab.w); v3 = fmaf(cXr, xv.w, v3);
                wxr[r][0] = fminf(fmaxf(v0, 0.f), WBc);
                wxr[r][1] = fminf(fmaxf(v1, 0.f), WBc);
                wxr[r][2] = fminf(fmaxf(v2, 0.f), WBc);
                wxr[r][3] = fminf(fmaxf(v3, 0.f), WBc);
            }
        }

        asm volatile("barrier.cluster.wait.aligned;" ::: "memory");
    }

    // --- final readout for t = Tn-1 (out(31) sits in buffer (Tn-1)&3 = 3) ---
    if (w == 15 || (w == 14 && rank == 0)) {
        const float* __restrict__ ew = (w == 15) ? s.effc : s.effv;
        const int ch = (w == 15) ? rank : 8;
        float p = 0.f;
        #pragma unroll 4
        for (int it = 0; it < 16; it++) {
            const int h = it * 32 + l;
            p = fmaf(ew[h], s.o[3][h], p);
        }
        p = warp_sum(p);
        if (l == 0) yout[((Tn - 1) * Bn + b) * 9 + ch] = p;
    }
}

extern "C" void kernel_launch(void* const* d_in, const int* in_sizes, int n_in,
                              void* d_out, int out_size) {
    (void)in_sizes; (void)n_in; (void)out_size;
    const size_t smem = sizeof(SM);
    cudaFuncSetAttribute(rnn_kernel, cudaFuncAttributeMaxDynamicSharedMemorySize, (int)smem);
    rnn_kernel<<<Bn * 8, 512, smem>>>(
        (const float*)d_in[0], (const float*)d_in[1], (const float*)d_in[2],
        (const float*)d_in[3], (const float*)d_in[4], (const float*)d_in[5],
        (const float*)d_in[6], (const float*)d_in[7], (const float*)d_in[8],
        (const float*)d_in[9], (float*)d_out);
}

// round 6
// speedup vs baseline: 1.6884x; 1.3148x over previous
#include <cuda_runtime.h>
#include <cstdint>

#define Bn   16
#define Tn   32
#define INn  112
#define Hn   512
#define NGn  7
#define En   409      // int(0.8*512)
#define EXn  410      // H - round(0.2*512)
#define AWc   0.02f
#define OMAWc 0.98f
#define AXc   0.2f
#define OMAXc 0.8f
#define DTc   0.02f

struct __align__(16) SM {
    float awbh[64 * Hn];    // alpha_w * relu(w_h2h) rows of this CTA   131072 B
    float wx[64 * INn];     // plastic input weights (thread-private)    28672 B
    float awbx[64 * INn];   // alpha_w * relu(w_x2h)                     28672 B
    float wa[NGn * Hn];     // plastic attn weights (warp-private)       14336 B
    float awba[NGn * Hn];   //                                           14336 B
    float effc[Hn];         // relu(w_h2o[rank]) * exist                  2048 B
    float effv[Hn];         // relu(w_h2v) * exist                        2048 B
    float o[4][Hn];         // out(tau) lives in o[tau & 3]               8192 B
    float logits2[2][8];
    float battn[8];
    float Rs[Tn];
};

__device__ __forceinline__ float warp_sum(float v) {
    v += __shfl_xor_sync(0xffffffffu, v, 16);
    v += __shfl_xor_sync(0xffffffffu, v, 8);
    v += __shfl_xor_sync(0xffffffffu, v, 4);
    v += __shfl_xor_sync(0xffffffffu, v, 2);
    v += __shfl_xor_sync(0xffffffffu, v, 1);
    return v;
}
__device__ __forceinline__ float warp_max(float v) {
    v = fmaxf(v, __shfl_xor_sync(0xffffffffu, v, 16));
    v = fmaxf(v, __shfl_xor_sync(0xffffffffu, v, 8));
    v = fmaxf(v, __shfl_xor_sync(0xffffffffu, v, 4));
    v = fmaxf(v, __shfl_xor_sync(0xffffffffu, v, 2));
    v = fmaxf(v, __shfl_xor_sync(0xffffffffu, v, 1));
    return v;
}
__device__ __forceinline__ unsigned int smem_u32(const void* p) {
    unsigned int a;
    asm("{ .reg .u64 t; cvta.to.shared.u64 t, %1; cvt.u32.u64 %0, t; }" : "=r"(a) : "l"(p));
    return a;
}
__device__ __forceinline__ void st_clu(unsigned int laddr, int rank, float v) {
    unsigned int ra;
    asm volatile("mapa.shared::cluster.u32 %0, %1, %2;" : "=r"(ra) : "r"(laddr), "r"(rank));
    asm volatile("st.shared::cluster.f32 [%0], %1;" :: "r"(ra), "f"(v) : "memory");
}
// tanh(relu(x)) with ~2-ulp fast exp/div; exact 1.0 beyond 15
__device__ __forceinline__ float tanh_relu_fast(float x) {
    float xr = fminf(fmaxf(x, 0.f), 15.f);
    float e2 = __expf(2.f * xr);
    return __fdividef(e2 - 1.f, e2 + 1.f);
}

__global__ void __launch_bounds__(512, 1) __cluster_dims__(8, 1, 1)
rnn_kernel(const float* __restrict__ x, const float* __restrict__ R,
           const float* __restrict__ w_x2h, const float* __restrict__ w_h2h,
           const float* __restrict__ b_h2h, const float* __restrict__ w_attn,
           const float* __restrict__ b_attn, const float* __restrict__ w_h2o,
           const float* __restrict__ w_h2v, const float* __restrict__ kappa,
           float* __restrict__ yout)
{
    extern __shared__ __align__(16) char smraw[];
    SM& s = *reinterpret_cast<SM*>(smraw);

    const int tid  = threadIdx.x;
    const int w    = tid >> 5;
    const int l    = tid & 31;
    const int rank = blockIdx.x & 7;
    const int b    = blockIdx.x >> 3;
    const int rl0  = w * 4;            // local row base in CTA (0..60)
    const int row0 = rank * 64 + rl0;  // global row base
    const int lk   = l * 4;            // column base within a 128-block
    const int g    = (w < 7) ? w : w - 7;   // attention group for warps < 14

    // ---------------- init ----------------
    if (tid < 8)  s.battn[tid] = (tid < NGn) ? b_attn[tid] : 0.f;
    if (tid < Tn) s.Rs[tid]    = R[tid * Bn + b];
    s.o[3][tid] = 0.f;                 // out(-1) = 0
    for (int i = tid; i < NGn * Hn; i += 512) {
        float v = fmaxf(w_attn[i], 0.f);
        s.wa[i] = v; s.awba[i] = AWc * v;
    }
    s.effc[tid] = (tid < EXn) ? fmaxf(w_h2o[rank * Hn + tid], 0.f) : 0.f;
    s.effv[tid] = (tid < EXn) ? fmaxf(w_h2v[tid], 0.f) : 0.f;

    // uniform kappa scalars
    const float k00 = kappa[0], k01 = kappa[1], k10 = kappa[2], k11 = kappa[3];
    const float kinAt = kappa[4 + 2 * (l >> 2)];
    const float kinBt = kappa[5 + 2 * (l >> 2)];
    const float kfb = (w < 14) ? kappa[18 + g / 3] : 0.f;

    float wh[4][16];
    float bh[4], wd[4], awbd[4], m3[4];
    bool  rhb[4];
    #pragma unroll
    for (int i = 0; i < 4; i++) m3[i] = (lk + i >= 25) ? 1.f : 0.f;

    #pragma unroll
    for (int r = 0; r < 4; r++) {
        const int row = row0 + r;
        bh[r]  = b_h2h[row];
        rhb[r] = (row >= En);
        float dv = fmaxf(w_h2h[row * Hn + row], 0.f);
        wd[r] = dv; awbd[r] = AWc * dv;
        #pragma unroll
        for (int c4 = 0; c4 < 4; c4++) {
            const int j0 = c4 * 128 + lk;
            float4 v = *reinterpret_cast<const float4*>(&w_h2h[row * Hn + j0]);
            v.x = fmaxf(v.x, 0.f); v.y = fmaxf(v.y, 0.f);
            v.z = fmaxf(v.z, 0.f); v.w = fmaxf(v.w, 0.f);
            wh[r][c4*4+0] = v.x; wh[r][c4*4+1] = v.y;
            wh[r][c4*4+2] = v.z; wh[r][c4*4+3] = v.w;
            *reinterpret_cast<float4*>(&s.awbh[(rl0 + r) * Hn + j0]) =
                make_float4(AWc*v.x, AWc*v.y, AWc*v.z, AWc*v.w);
        }
        if (l < 28) {
            float4 v = *reinterpret_cast<const float4*>(&w_x2h[row * INn + lk]);
            v.x = fmaxf(v.x, 0.f); v.y = fmaxf(v.y, 0.f);
            v.z = fmaxf(v.z, 0.f); v.w = fmaxf(v.w, 0.f);
            *reinterpret_cast<float4*>(&s.wx[(rl0 + r) * INn + lk]) = v;
            *reinterpret_cast<float4*>(&s.awbx[(rl0 + r) * INn + lk]) =
                make_float4(AWc*v.x, AWc*v.y, AWc*v.z, AWc*v.w);
        }
    }

    float state[4] = {0.f, 0.f, 0.f, 0.f};
    float attn_g = 0.f;

    __syncthreads();
    asm volatile("barrier.cluster.arrive.aligned;" ::: "memory");
    asm volatile("barrier.cluster.wait.aligned;"   ::: "memory");

    // ---------------- time loop ----------------
    for (int t = 0; t < Tn; t++) {
        const int pb = (t + 3) & 3;    // buffer holding out(t-1)
        const int cb = t & 3;          // buffer receiving out(t)
        const float dtR = DTc * s.Rs[t];
        const float* __restrict__ op = s.o[pb];

        // prefetch x(t) early (L2-resident after warmup)
        float4 xv = make_float4(0.f, 0.f, 0.f, 0.f);
        if (l < 28) xv = *reinterpret_cast<const float4*>(&x[(t * Bn + b) * INn + lk]);

        // --- phase 1: fused wa update (deferred from t-1) + logits; readout t-1 ---
        if (w < 14) {
            const float hbg = ((t > 0) ? DTc * s.Rs[t - 1] : 0.f) * kfb * attn_g;
            const int h0 = (w < 7) ? 0 : 256;
            float* __restrict__ war  = &s.wa[g * Hn];
            const float* __restrict__ abr = &s.awba[g * Hn];
            float p = 0.f;
            #pragma unroll
            for (int it = 0; it < 8; it++) {
                const int h = h0 + it * 32 + l;
                const float ov = op[h];
                const float hedge = (h < En) ? ov : 0.f;
                float v = fmaf(war[h], OMAWc, abr[h]);
                v = fmaf(hbg, hedge, v);
                v = fmaxf(v, 0.f);
                war[h] = v;
                const float osm = (h < EXn) ? ((h < En) ? ov : -ov) : 0.f;
                p = fmaf(v, osm, p);
            }
            p = warp_sum(p);
            if (l == 0) s.logits2[w >= 7][g] = p;
        } else if (t > 0 && (w == 15 || (w == 14 && rank == 0))) {
            const float* __restrict__ ew = (w == 15) ? s.effc : s.effv;
            const int ch = (w == 15) ? rank : 8;
            float p = 0.f;
            #pragma unroll 4
            for (int it = 0; it < 16; it++) {
                const int h = it * 32 + l;
                p = fmaf(ew[h], op[h], p);
            }
            p = warp_sum(p);
            if (l == 0) yout[((t - 1) * Bn + b) * 9 + ch] = p;
        }
        __syncthreads();

        // --- softmax replicated in every warp (attn stays in registers) ---
        float gate;
        {
            float L = (l < NGn) ? s.logits2[0][l] + s.logits2[1][l] + s.battn[l] : -3.4e38f;
            float mx = warp_max(L);
            float e = (l < NGn) ? __expf(L - mx) : 0.f;
            float ssum = warp_sum(e);
            float a = __fdividef(e, ssum);
            attn_g = __shfl_sync(0xffffffffu, a, g);
            gate   = __shfl_sync(0xffffffffu, a, l >> 2);
        }
        if (l < 28) { xv.x *= gate; xv.y *= gate; xv.z *= gate; xv.w *= gate; }

        // --- recurrent + input matvec (sign applied analytically on c4==3) ---
        float part[4] = {0.f, 0.f, 0.f, 0.f};
        #pragma unroll
        for (int c4 = 0; c4 < 4; c4++) {
            float4 ov = *reinterpret_cast<const float4*>(&op[c4 * 128 + lk]);
            if (c4 == 3) {   // sign boundary at j = 409 (j = 384 + lk + i)
                ov.x = fmaf(m3[0], -2.f * ov.x, ov.x);
                ov.y = fmaf(m3[1], -2.f * ov.y, ov.y);
                ov.z = fmaf(m3[2], -2.f * ov.z, ov.z);
                ov.w = fmaf(m3[3], -2.f * ov.w, ov.w);
            }
            #pragma unroll
            for (int r = 0; r < 4; r++) {
                part[r] = fmaf(wh[r][c4*4+0], ov.x, part[r]);
                part[r] = fmaf(wh[r][c4*4+1], ov.y, part[r]);
                part[r] = fmaf(wh[r][c4*4+2], ov.z, part[r]);
                part[r] = fmaf(wh[r][c4*4+3], ov.w, part[r]);
            }
        }
        if (l < 28) {
            #pragma unroll
            for (int r = 0; r < 4; r++) {
                const float4 wxv = *reinterpret_cast<const float4*>(
                    &s.wx[(rl0 + r) * INn + lk]);
                part[r] = fmaf(wxv.x, xv.x, part[r]);
                part[r] = fmaf(wxv.y, xv.y, part[r]);
                part[r] = fmaf(wxv.z, xv.z, part[r]);
                part[r] = fmaf(wxv.w, xv.w, part[r]);
            }
        }

        // --- reduce, state update, out(t) ---
        float base[4], orow[4];
        #pragma unroll
        for (int r = 0; r < 4; r++) {
            float tot = warp_sum(part[r]);
            orow[r] = op[row0 + r];
            const float osrow = rhb[r] ? -orow[r] : orow[r];
            tot = tot - wd[r] * osrow + bh[r];      // remove diagonal, add bias
            state[r] = fmaf(AXc, tot, OMAXc * state[r]);
        }
        float tv;
        {
            float st = (l == 0) ? state[0] : (l == 1) ? state[1] : (l == 2) ? state[2] : state[3];
            tv = tanh_relu_fast(st);
            #pragma unroll
            for (int r = 0; r < 4; r++)
                base[r] = dtR * __shfl_sync(0xffffffffu, tv, r);
        }

        // --- push out(t) to all 8 cluster CTAs (lane l -> row l&3, rank l>>2) ---
        {
            const int rr  = l & 3;
            const int trk = l >> 2;
            const float val = __shfl_sync(0xffffffffu, tv, rr);
            st_clu(smem_u32(&s.o[cb][row0 + rr]), trk, val);
        }

        asm volatile("barrier.cluster.arrive.aligned;" ::: "memory");

        // --- plastic wh/wx updates (hidden behind the cluster barrier) ---
        // safe to reload op after arrive: peers overwrite buffer pb only at
        // their step t+3 push, which requires our arrive(t+2).
        float cA[4], cB[4];
        #pragma unroll
        for (int r = 0; r < 4; r++) {
            cA[r] = base[r] * (rhb[r] ? k10 : k00);
            cB[r] = base[r] * (rhb[r] ? k11 : k01);
        }
        #pragma unroll
        for (int c4 = 0; c4 < 3; c4++) {        // uniform column-half tiles
            const float4 ov = *reinterpret_cast<const float4*>(&op[c4 * 128 + lk]);
            #pragma unroll
            for (int r = 0; r < 4; r++) {
                const float4 ab = *reinterpret_cast<const float4*>(
                    &s.awbh[(rl0 + r) * Hn + c4 * 128 + lk]);
                float v0 = fmaf(wh[r][c4*4+0], OMAWc, ab.x); v0 = fmaf(cA[r], ov.x, v0);
                float v1 = fmaf(wh[r][c4*4+1], OMAWc, ab.y); v1 = fmaf(cA[r], ov.y, v1);
                float v2 = fmaf(wh[r][c4*4+2], OMAWc, ab.z); v2 = fmaf(cA[r], ov.z, v2);
                float v3 = fmaf(wh[r][c4*4+3], OMAWc, ab.w); v3 = fmaf(cA[r], ov.w, v3);
                wh[r][c4*4+0] = fmaxf(v0, 0.f);
                wh[r][c4*4+1] = fmaxf(v1, 0.f);
                wh[r][c4*4+2] = fmaxf(v2, 0.f);
                wh[r][c4*4+3] = fmaxf(v3, 0.f);
            }
        }
        {   // c4 == 3: mixed column-half tile
            const float4 ov = *reinterpret_cast<const float4*>(&op[384 + lk]);
            #pragma unroll
            for (int r = 0; r < 4; r++) {
                const float4 ab = *reinterpret_cast<const float4*>(
                    &s.awbh[(rl0 + r) * Hn + 384 + lk]);
                const float dc = cB[r] - cA[r];
                const float c0 = fmaf(m3[0], dc, cA[r]);
                const float c1 = fmaf(m3[1], dc, cA[r]);
                const float c2 = fmaf(m3[2], dc, cA[r]);
                const float c3 = fmaf(m3[3], dc, cA[r]);
                float v0 = fmaf(wh[r][12], OMAWc, ab.x); v0 = fmaf(c0, ov.x, v0);
                float v1 = fmaf(wh[r][13], OMAWc, ab.y); v1 = fmaf(c1, ov.y, v1);
                float v2 = fmaf(wh[r][14], OMAWc, ab.z); v2 = fmaf(c2, ov.z, v2);
                float v3 = fmaf(wh[r][15], OMAWc, ab.w); v3 = fmaf(c3, ov.w, v3);
                wh[r][12] = fmaxf(v0, 0.f);
                wh[r][13] = fmaxf(v1, 0.f);
                wh[r][14] = fmaxf(v2, 0.f);
                wh[r][15] = fmaxf(v3, 0.f);
            }
        }
        // diagonal shadow: identical recurrence to its (masked-out) array slot
        #pragma unroll
        for (int r = 0; r < 4; r++) {
            const float cd = rhb[r] ? cB[r] : cA[r];
            float v = fmaf(wd[r], OMAWc, awbd[r]);
            v = fmaf(cd, orow[r], v);
            wd[r] = fmaxf(v, 0.f);
        }
        if (l < 28) {
            #pragma unroll
            for (int r = 0; r < 4; r++) {
                const float4 wxv = *reinterpret_cast<const float4*>(
                    &s.wx[(rl0 + r) * INn + lk]);
                const float4 ab = *reinterpret_cast<const float4*>(
                    &s.awbx[(rl0 + r) * INn + lk]);
                const float cX = base[r] * (rhb[r] ? kinBt : kinAt);
                float v0 = fmaf(wxv.x, OMAWc, ab.x); v0 = fmaf(cX, xv.x, v0);
                float v1 = fmaf(wxv.y, OMAWc, ab.y); v1 = fmaf(cX, xv.y, v1);
                float v2 = fmaf(wxv.z, OMAWc, ab.z); v2 = fmaf(cX, xv.z, v2);
                float v3 = fmaf(wxv.w, OMAWc, ab.w); v3 = fmaf(cX, xv.w, v3);
                *reinterpret_cast<float4*>(&s.wx[(rl0 + r) * INn + lk]) =
                    make_float4(fmaxf(v0, 0.f), fmaxf(v1, 0.f),
                                fmaxf(v2, 0.f), fmaxf(v3, 0.f));
            }
        }

        asm volatile("barrier.cluster.wait.aligned;" ::: "memory");
    }

    // --- final readout for t = Tn-1 (out(31) sits in buffer (Tn-1)&3 = 3) ---
    if (w == 15 || (w == 14 && rank == 0)) {
        const float* __restrict__ ew = (w == 15) ? s.effc : s.effv;
        const int ch = (w == 15) ? rank : 8;
        float p = 0.f;
        #pragma unroll 4
        for (int it = 0; it < 16; it++) {
            const int h = it * 32 + l;
            p = fmaf(ew[h], s.o[3][h], p);
        }
        p = warp_sum(p);
        if (l == 0) yout[((Tn - 1) * Bn + b) * 9 + ch] = p;
    }
}

extern "C" void kernel_launch(void* const* d_in, const int* in_sizes, int n_in,
                              void* d_out, int out_size) {
    (void)in_sizes; (void)n_in; (void)out_size;
    const size_t smem = sizeof(SM);
    cudaFuncSetAttribute(rnn_kernel, cudaFuncAttributeMaxDynamicSharedMemorySize, (int)smem);
    rnn_kernel<<<Bn * 8, 512, smem>>>(
        (const float*)d_in[0], (const float*)d_in[1], (const float*)d_in[2],
        (const float*)d_in[3], (const float*)d_in[4], (const float*)d_in[5],
        (const float*)d_in[6], (const float*)d_in[7], (const float*)d_in[8],
        (const float*)d_in[9], (float*)d_out);
}

// round 7
// speedup vs baseline: 1.6985x; 1.0059x over previous
#include <cuda_runtime.h>
#include <cstdint>

#define Bn   16
#define Tn   32
#define INn  112
#define Hn   512
#define NGn  7
#define En   409      // int(0.8*512)
#define EXn  410      // H - round(0.2*512)
#define AWc   0.02f
#define OMAWc 0.98f
#define AXc   0.2f
#define OMAXc 0.8f
#define DTc   0.02f

struct __align__(16) SM {
    float awbh[64 * Hn];    // alpha_w * relu(w_h2h) rows of this CTA   131072 B
    float wx[64 * INn];     // plastic input weights (thread-private)    28672 B
    float awbx[64 * INn];   // alpha_w * relu(w_x2h)                     28672 B
    float wa[NGn * Hn];     // plastic attn weights                      14336 B
    float awba[NGn * Hn];   //                                           14336 B
    float effc[Hn];         // relu(w_h2o[rank]) * exist                  2048 B
    float effv[Hn];         // relu(w_h2v) * exist                        2048 B
    float o[4][Hn];         // out(tau) lives in o[tau & 3]               8192 B
    float rowdat[64 * 4];   // per local row: {bh, awbd, wd, pad}         1024 B
    float logits2[2][8];
    float battn[8];
    float Rs[Tn];
};

__device__ __forceinline__ float warp_sum(float v) {
    v += __shfl_xor_sync(0xffffffffu, v, 16);
    v += __shfl_xor_sync(0xffffffffu, v, 8);
    v += __shfl_xor_sync(0xffffffffu, v, 4);
    v += __shfl_xor_sync(0xffffffffu, v, 2);
    v += __shfl_xor_sync(0xffffffffu, v, 1);
    return v;
}
__device__ __forceinline__ unsigned int smem_u32(const void* p) {
    unsigned int a;
    asm("{ .reg .u64 t; cvta.to.shared.u64 t, %1; cvt.u32.u64 %0, t; }" : "=r"(a) : "l"(p));
    return a;
}
__device__ __forceinline__ void st_clu(unsigned int laddr, int rank, float v) {
    unsigned int ra;
    asm volatile("mapa.shared::cluster.u32 %0, %1, %2;" : "=r"(ra) : "r"(laddr), "r"(rank));
    asm volatile("st.shared::cluster.f32 [%0], %1;" :: "r"(ra), "f"(v) : "memory");
}
// tanh(relu(x)) with fast exp/div; exact saturation beyond 15
__device__ __forceinline__ float tanh_relu_fast(float x) {
    float xr = fminf(fmaxf(x, 0.f), 15.f);
    float e2 = __expf(2.f * xr);
    return __fdividef(e2 - 1.f, e2 + 1.f);
}

__global__ void __launch_bounds__(512, 1) __cluster_dims__(8, 1, 1)
rnn_kernel(const float* __restrict__ x, const float* __restrict__ R,
           const float* __restrict__ w_x2h, const float* __restrict__ w_h2h,
           const float* __restrict__ b_h2h, const float* __restrict__ w_attn,
           const float* __restrict__ b_attn, const float* __restrict__ w_h2o,
           const float* __restrict__ w_h2v, const float* __restrict__ kappa,
           float* __restrict__ yout)
{
    extern __shared__ __align__(16) char smraw[];
    SM& s = *reinterpret_cast<SM*>(smraw);

    const int tid  = threadIdx.x;
    const int w    = tid >> 5;
    const int l    = tid & 31;
    const int rank = blockIdx.x & 7;
    const int b    = blockIdx.x >> 3;
    const int rl0  = w * 4;            // local row base in CTA (0..60)
    const int row0 = rank * 64 + rl0;  // global row base
    const int lk   = l * 4;            // column base within a 128-block
    const int g    = (w < 7) ? w : w - 7;   // attention group for warps < 14

    // ---------------- init ----------------
    if (tid < 8)  s.battn[tid] = (tid < NGn) ? b_attn[tid] : 0.f;
    if (tid < Tn) s.Rs[tid]    = R[tid * Bn + b];
    s.o[3][tid] = 0.f;                 // out(-1) = 0
    for (int i = tid; i < NGn * Hn; i += 512) {
        float v = fmaxf(w_attn[i], 0.f);
        s.wa[i] = v; s.awba[i] = AWc * v;
    }
    s.effc[tid] = (tid < EXn) ? fmaxf(w_h2o[rank * Hn + tid], 0.f) : 0.f;
    s.effv[tid] = (tid < EXn) ? fmaxf(w_h2v[tid], 0.f) : 0.f;
    if (l < 4) {
        const int row = row0 + l;
        const float dv = fmaxf(w_h2h[row * Hn + row], 0.f);
        s.rowdat[(rl0 + l) * 4 + 0] = b_h2h[row];
        s.rowdat[(rl0 + l) * 4 + 1] = AWc * dv;
        s.rowdat[(rl0 + l) * 4 + 2] = dv;
        s.rowdat[(rl0 + l) * 4 + 3] = 0.f;
    }

    // uniform kappa scalars
    const float k00 = kappa[0], k01 = kappa[1], k10 = kappa[2], k11 = kappa[3];
    const float kinAt = kappa[4 + 2 * (l >> 2)];
    const float kinBt = kappa[5 + 2 * (l >> 2)];
    const float kfb = (w < 14) ? kappa[18 + g / 3] : 0.f;

    float wh[4][16];
    #pragma unroll
    for (int r = 0; r < 4; r++) {
        const int row = row0 + r;
        #pragma unroll
        for (int c4 = 0; c4 < 4; c4++) {
            const int j0 = c4 * 128 + lk;
            float4 v = *reinterpret_cast<const float4*>(&w_h2h[row * Hn + j0]);
            v.x = fmaxf(v.x, 0.f); v.y = fmaxf(v.y, 0.f);
            v.z = fmaxf(v.z, 0.f); v.w = fmaxf(v.w, 0.f);
            wh[r][c4*4+0] = v.x; wh[r][c4*4+1] = v.y;
            wh[r][c4*4+2] = v.z; wh[r][c4*4+3] = v.w;
            *reinterpret_cast<float4*>(&s.awbh[(rl0 + r) * Hn + j0]) =
                make_float4(AWc*v.x, AWc*v.y, AWc*v.z, AWc*v.w);
        }
        if (l < 28) {
            float4 v = *reinterpret_cast<const float4*>(&w_x2h[row * INn + lk]);
            v.x = fmaxf(v.x, 0.f); v.y = fmaxf(v.y, 0.f);
            v.z = fmaxf(v.z, 0.f); v.w = fmaxf(v.w, 0.f);
            *reinterpret_cast<float4*>(&s.wx[(rl0 + r) * INn + lk]) = v;
            *reinterpret_cast<float4*>(&s.awbx[(rl0 + r) * INn + lk]) =
                make_float4(AWc*v.x, AWc*v.y, AWc*v.z, AWc*v.w);
        }
    }

    float state[4] = {0.f, 0.f, 0.f, 0.f};
    float attn_g = 0.f;

    __syncthreads();
    asm volatile("barrier.cluster.arrive.aligned;" ::: "memory");
    asm volatile("barrier.cluster.wait.aligned;"   ::: "memory");

    // ---------------- time loop ----------------
    for (int t = 0; t < Tn; t++) {
        const int pb = (t + 3) & 3;    // buffer holding out(t-1)
        const int cb = t & 3;          // buffer receiving out(t)
        const float dtR = DTc * s.Rs[t];
        const float* __restrict__ op = s.o[pb];

        // prefetch x(t) early (L2-resident after warmup)
        float4 xv = make_float4(0.f, 0.f, 0.f, 0.f);
        if (l < 28) xv = *reinterpret_cast<const float4*>(&x[(t * Bn + b) * INn + lk]);

        // --- phase 1: fused wa update (deferred from t-1) + logits; readout t-1 ---
        if (w < 14) {
            const float hbg = ((t > 0) ? DTc * s.Rs[t - 1] : 0.f) * kfb * attn_g;
            const int h0 = (w < 7) ? 0 : 256;
            float* __restrict__ war  = &s.wa[g * Hn];
            const float* __restrict__ abr = &s.awba[g * Hn];
            float p = 0.f;
            #pragma unroll
            for (int it = 0; it < 8; it++) {
                const int h = h0 + it * 32 + l;
                const float ov = op[h];
                const float hedge = (h < En) ? ov : 0.f;
                float v = fmaf(war[h], OMAWc, abr[h]);
                v = fmaf(hbg, hedge, v);
                v = fmaxf(v, 0.f);
                war[h] = v;
                const float osm = (h < EXn) ? ((h < En) ? ov : -ov) : 0.f;
                p = fmaf(v, osm, p);
            }
            p = warp_sum(p);
            if (l == 0) s.logits2[w >= 7][g] = p;
        } else if (t > 0 && (w == 15 || (w == 14 && rank == 0))) {
            const float* __restrict__ ew = (w == 15) ? s.effc : s.effv;
            const int ch = (w == 15) ? rank : 8;
            float p = 0.f;
            #pragma unroll 4
            for (int it = 0; it < 16; it++) {
                const int h = it * 32 + l;
                p = fmaf(ew[h], op[h], p);
            }
            p = warp_sum(p);
            if (l == 0) yout[((t - 1) * Bn + b) * 9 + ch] = p;
        }
        __syncthreads();

        // --- softmax replicated in every warp (constant-shift, no max pass) ---
        float gate;
        {
            const float L = (l < NGn)
                ? s.logits2[0][l] + s.logits2[1][l] + s.battn[l] : 0.f;
            const float e = (l < NGn) ? __expf(L - 20.f) : 0.f;
            const float ssum = warp_sum(e);
            const float a = __fdividef(e, ssum);
            attn_g = __shfl_sync(0xffffffffu, a, g);
            gate   = __shfl_sync(0xffffffffu, a, l >> 2);
        }
        if (l < 28) { xv.x *= gate; xv.y *= gate; xv.z *= gate; xv.w *= gate; }

        // --- recurrent + input matvec (sign applied analytically on c4==3) ---
        float part[4] = {0.f, 0.f, 0.f, 0.f};
        #pragma unroll
        for (int c4 = 0; c4 < 4; c4++) {
            float4 ov = *reinterpret_cast<const float4*>(&op[c4 * 128 + lk]);
            if (c4 == 3) {   // sign boundary at j = 409 (j = 384 + lk + i)
                if (lk + 0 >= 25) ov.x = -ov.x;
                if (lk + 1 >= 25) ov.y = -ov.y;
                if (lk + 2 >= 25) ov.z = -ov.z;
                if (lk + 3 >= 25) ov.w = -ov.w;
            }
            #pragma unroll
            for (int r = 0; r < 4; r++) {
                part[r] = fmaf(wh[r][c4*4+0], ov.x, part[r]);
                part[r] = fmaf(wh[r][c4*4+1], ov.y, part[r]);
                part[r] = fmaf(wh[r][c4*4+2], ov.z, part[r]);
                part[r] = fmaf(wh[r][c4*4+3], ov.w, part[r]);
            }
        }
        if (l < 28) {
            #pragma unroll
            for (int r = 0; r < 4; r++) {
                const float4 wxv = *reinterpret_cast<const float4*>(
                    &s.wx[(rl0 + r) * INn + lk]);
                part[r] = fmaf(wxv.x, xv.x, part[r]);
                part[r] = fmaf(wxv.y, xv.y, part[r]);
                part[r] = fmaf(wxv.z, xv.z, part[r]);
                part[r] = fmaf(wxv.w, xv.w, part[r]);
            }
        }

        // --- reduce, state update, out(t) ---
        float base[4];
        #pragma unroll
        for (int r = 0; r < 4; r++) {
            float tot = warp_sum(part[r]);
            const float4 rd = *reinterpret_cast<const float4*>(&s.rowdat[(rl0 + r) * 4]);
            const float orow = op[row0 + r];
            const float osrow = (row0 + r >= En) ? -orow : orow;
            tot = tot - rd.z * osrow + rd.x;        // remove diagonal, add bias
            state[r] = fmaf(AXc, tot, OMAXc * state[r]);
        }
        float tv;
        {
            float st = (l == 0) ? state[0] : (l == 1) ? state[1] : (l == 2) ? state[2] : state[3];
            tv = tanh_relu_fast(st);
            #pragma unroll
            for (int r = 0; r < 4; r++)
                base[r] = dtR * __shfl_sync(0xffffffffu, tv, r);
        }

        // --- push out(t) to all 8 cluster CTAs (lane l -> row l&3, rank l>>2) ---
        {
            const int rr  = l & 3;
            const int trk = l >> 2;
            const float val = __shfl_sync(0xffffffffu, tv, rr);
            st_clu(smem_u32(&s.o[cb][row0 + rr]), trk, val);
        }

        asm volatile("barrier.cluster.arrive.aligned;" ::: "memory");

        // --- plastic wh/wx updates (hidden behind the cluster barrier) ---
        // safe to reload op after arrive: peers overwrite buffer pb only at
        // their step t+3 push, which requires our arrive(t+2).
        #pragma unroll
        for (int c4 = 0; c4 < 3; c4++) {        // uniform column-half tiles
            const float4 ov = *reinterpret_cast<const float4*>(&op[c4 * 128 + lk]);
            #pragma unroll
            for (int r = 0; r < 4; r++) {
                const float cAr = base[r] * ((row0 + r >= En) ? k10 : k00);
                const float4 ab = *reinterpret_cast<const float4*>(
                    &s.awbh[(rl0 + r) * Hn + c4 * 128 + lk]);
                float v0 = fmaf(wh[r][c4*4+0], OMAWc, ab.x); v0 = fmaf(cAr, ov.x, v0);
                float v1 = fmaf(wh[r][c4*4+1], OMAWc, ab.y); v1 = fmaf(cAr, ov.y, v1);
                float v2 = fmaf(wh[r][c4*4+2], OMAWc, ab.z); v2 = fmaf(cAr, ov.z, v2);
                float v3 = fmaf(wh[r][c4*4+3], OMAWc, ab.w); v3 = fmaf(cAr, ov.w, v3);
                wh[r][c4*4+0] = fmaxf(v0, 0.f);
                wh[r][c4*4+1] = fmaxf(v1, 0.f);
                wh[r][c4*4+2] = fmaxf(v2, 0.f);
                wh[r][c4*4+3] = fmaxf(v3, 0.f);
            }
        }
        {   // c4 == 3: mixed column-half tile (boundary at lk + i >= 25)
            const float4 ov = *reinterpret_cast<const float4*>(&op[384 + lk]);
            #pragma unroll
            for (int r = 0; r < 4; r++) {
                const bool rhbr = (row0 + r >= En);
                const float cAr = base[r] * (rhbr ? k10 : k00);
                const float cBr = base[r] * (rhbr ? k11 : k01);
                const float4 ab = *reinterpret_cast<const float4*>(
                    &s.awbh[(rl0 + r) * Hn + 384 + lk]);
                const float c0 = (lk + 0 >= 25) ? cBr : cAr;
                const float c1 = (lk + 1 >= 25) ? cBr : cAr;
                const float c2 = (lk + 2 >= 25) ? cBr : cAr;
                const float c3 = (lk + 3 >= 25) ? cBr : cAr;
                float v0 = fmaf(wh[r][12], OMAWc, ab.x); v0 = fmaf(c0, ov.x, v0);
                float v1 = fmaf(wh[r][13], OMAWc, ab.y); v1 = fmaf(c1, ov.y, v1);
                float v2 = fmaf(wh[r][14], OMAWc, ab.z); v2 = fmaf(c2, ov.z, v2);
                float v3 = fmaf(wh[r][15], OMAWc, ab.w); v3 = fmaf(c3, ov.w, v3);
                wh[r][12] = fmaxf(v0, 0.f);
                wh[r][13] = fmaxf(v1, 0.f);
                wh[r][14] = fmaxf(v2, 0.f);
                wh[r][15] = fmaxf(v3, 0.f);
            }
        }
        // diagonal shadow (lane 0 only; visible to next step via its __syncthreads)
        if (l == 0) {
            #pragma unroll
            for (int r = 0; r < 4; r++) {
                const bool rhbr = (row0 + r >= En);
                const float cd = base[r] * (rhbr ? k11 : k00);
                const float awbd = s.rowdat[(rl0 + r) * 4 + 1];
                const float wdv  = s.rowdat[(rl0 + r) * 4 + 2];
                float v = fmaf(wdv, OMAWc, awbd);
                v = fmaf(cd, op[row0 + r], v);
                s.rowdat[(rl0 + r) * 4 + 2] = fmaxf(v, 0.f);
            }
        }
        if (l < 28) {
            #pragma unroll
            for (int r = 0; r < 4; r++) {
                const float4 wxv = *reinterpret_cast<const float4*>(
                    &s.wx[(rl0 + r) * INn + lk]);
                const float4 ab = *reinterpret_cast<const float4*>(
                    &s.awbx[(rl0 + r) * INn + lk]);
                const float cX = base[r] * ((row0 + r >= En) ? kinBt : kinAt);
                float v0 = fmaf(wxv.x, OMAWc, ab.x); v0 = fmaf(cX, xv.x, v0);
                float v1 = fmaf(wxv.y, OMAWc, ab.y); v1 = fmaf(cX, xv.y, v1);
                float v2 = fmaf(wxv.z, OMAWc, ab.z); v2 = fmaf(cX, xv.z, v2);
                float v3 = fmaf(wxv.w, OMAWc, ab.w); v3 = fmaf(cX, xv.w, v3);
                *reinterpret_cast<float4*>(&s.wx[(rl0 + r) * INn + lk]) =
                    make_float4(fmaxf(v0, 0.f), fmaxf(v1, 0.f),
                                fmaxf(v2, 0.f), fmaxf(v3, 0.f));
            }
        }

        asm volatile("barrier.cluster.wait.aligned;" ::: "memory");
    }

    // --- final readout for t = Tn-1 (out(31) sits in buffer (Tn-1)&3 = 3) ---
    if (w == 15 || (w == 14 && rank == 0)) {
        const float* __restrict__ ew = (w == 15) ? s.effc : s.effv;
        const int ch = (w == 15) ? rank : 8;
        float p = 0.f;
        #pragma unroll 4
        for (int it = 0; it < 16; it++) {
            const int h = it * 32 + l;
            p = fmaf(ew[h], s.o[3][h], p);
        }
        p = warp_sum(p);
        if (l == 0) yout[((Tn - 1) * Bn + b) * 9 + ch] = p;
    }
}

extern "C" void kernel_launch(void* const* d_in, const int* in_sizes, int n_in,
                              void* d_out, int out_size) {
    (void)in_sizes; (void)n_in; (void)out_size;
    const size_t smem = sizeof(SM);
    cudaFuncSetAttribute(rnn_kernel, cudaFuncAttributeMaxDynamicSharedMemorySize, (int)smem);
    rnn_kernel<<<Bn * 8, 512, smem>>>(
        (const float*)d_in[0], (const float*)d_in[1], (const float*)d_in[2],
        (const float*)d_in[3], (const float*)d_in[4], (const float*)d_in[5],
        (const float*)d_in[6], (const float*)d_in[7], (const float*)d_in[8],
        (const float*)d_in[9], (float*)d_out);
}